// round 6
// baseline (speedup 1.0000x reference)
#include <cuda_runtime.h>

#define T_STEPS 500
#define N_NEUR  20000
#define NPAIR   (N_NEUR / 2)     // 10000 threads, 2 adjacent neurons each
#define DT      0.1f
#define UNROLL  10               // 500 = 10 * 50
#define NBLK    (T_STEPS / UNROLL)

__device__ __forceinline__ float fast_tanh(float t) {
    float r;
    asm("tanh.approx.f32 %0, %1;" : "=f"(r) : "f"(t));
    return r;
}

struct HHConst {
    float p_c1, p_c0, q_c1, q_c0, n_c1, n_c0, f_c1, f_c0, e_c1, e_c0, h_c1, h_c0;
    float Ap, Bp, Aq, Bq, An, Bn, Af, Bf, Ae, Be;
    float h_a, h_b;
    float g_Ca, g_Ks, g_Kf, g_L, E_Ca, E_K, E_L;
    float dt_over_Cm, cdecay, rho_dt;
};

// one HH timestep for one neuron; fully inlined, two calls interleave via ptxas
__device__ __forceinline__ void hh_step(
    const HHConst& C, float icur,
    float& V, float& p, float& q, float& nn, float& e, float& f, float& cac)
{
    // h from OLD cac
    const float h = fmaf(C.h_b, fast_tanh(fmaf(cac, C.h_c1, C.h_c0)), C.h_a);

    const float gef  = C.g_Ca * e * e * f * h;
    const float i_ca = gef * (V - C.E_Ca);
    const float VmEK = V - C.E_K;
    const float i_ks = C.g_Ks * nn * VmEK;
    const float p2   = p * p;
    const float i_kf = C.g_Kf * p2 * p2 * q * VmEK;
    const float i_l  = C.g_L * (V - C.E_L);

    const float itot = icur - ((i_ca + i_ks) + (i_kf + i_l));
    const float dV   = itot * C.dt_over_Cm;
    V += dV;

    // i_ca2 = gef*(V_new - E_Ca) = i_ca + gef*dV
    const float i_ca2 = fmaf(gef, dV, i_ca);
    cac = fmaf(cac, C.cdecay, -i_ca2 * C.rho_dt);

    // 5 independent gate chains on UPDATED V
    p  = fmaf(C.Bp, fast_tanh(fmaf(V, C.p_c1, C.p_c0)), fmaf(C.Ap, p,  C.Bp));
    q  = fmaf(C.Bq, fast_tanh(fmaf(V, C.q_c1, C.q_c0)), fmaf(C.Aq, q,  C.Bq));
    e  = fmaf(C.Be, fast_tanh(fmaf(V, C.e_c1, C.e_c0)), fmaf(C.Ae, e,  C.Be));
    f  = fmaf(C.Bf, fast_tanh(fmaf(V, C.f_c1, C.f_c0)), fmaf(C.Af, f,  C.Bf));
    nn = fmaf(C.Bn, fast_tanh(fmaf(V, C.n_c1, C.n_c0)), fmaf(C.An, nn, C.Bn));
}

__global__ void __launch_bounds__(32, 1) hh_kernel(
    const float* __restrict__ i_inj,   // [T, N]
    const float* __restrict__ x0,      // [7, N]
    const float* __restrict__ params,  // [28]
    float* __restrict__ out)           // [T, 7, N]
{
    const int pi = blockIdx.x * 32 + threadIdx.x;   // pair index
    if (pi >= NPAIR) return;
    const int n2 = 2 * pi;                          // first neuron of the pair

    // ---- fold constants once
    HHConst C;
    {
        const float decay_ca = params[0];
        const float rho_ca   = params[1];
        const float p_tau = params[2],  p_scale = params[3],  p_mdp = params[4];
        const float q_tau = params[5],  q_scale = params[6],  q_mdp = params[7];
        const float n_tau = params[8],  n_scale = params[9],  n_mdp = params[10];
        const float f_tau = params[11], f_scale = params[12], f_mdp = params[13];
        const float e_tau = params[14], e_scale = params[15], e_mdp = params[16];
        const float h_alpha = params[17], h_scale = params[18], h_mdp = params[19];
        const float C_m = params[20];
        C.g_Ca = params[21]; C.g_Ks = params[22]; C.g_Kf = params[23]; C.g_L = params[24];
        C.E_Ca = params[25]; C.E_K  = params[26]; C.E_L  = params[27];

        C.p_c1 = 0.5f / p_scale; C.p_c0 = -p_mdp * 0.5f / p_scale;
        C.q_c1 = 0.5f / q_scale; C.q_c0 = -q_mdp * 0.5f / q_scale;
        C.n_c1 = 0.5f / n_scale; C.n_c0 = -n_mdp * 0.5f / n_scale;
        C.f_c1 = 0.5f / f_scale; C.f_c0 = -f_mdp * 0.5f / f_scale;
        C.e_c1 = 0.5f / e_scale; C.e_c0 = -e_mdp * 0.5f / e_scale;
        C.h_c1 = 0.5f / h_scale; C.h_c0 = -h_mdp * 0.5f / h_scale;

        C.Ap = p_tau / (p_tau + DT); C.Bp = 0.5f * DT / (p_tau + DT);
        C.Aq = q_tau / (q_tau + DT); C.Bq = 0.5f * DT / (q_tau + DT);
        C.An = n_tau / (n_tau + DT); C.Bn = 0.5f * DT / (n_tau + DT);
        C.Af = f_tau / (f_tau + DT); C.Bf = 0.5f * DT / (f_tau + DT);
        C.Ae = e_tau / (e_tau + DT); C.Be = 0.5f * DT / (e_tau + DT);

        C.h_b = 0.5f * h_alpha;
        C.h_a = 1.0f - C.h_b;
        C.dt_over_Cm = DT / C_m;
        C.cdecay = 1.0f - DT / decay_ca;
        C.rho_dt = rho_ca * DT;
    }

    // ---- initial state for both neurons (float2 loads, 8B-aligned since n2 even)
    float2 V   = *(const float2*)(x0 + 0 * N_NEUR + n2);
    float2 p   = *(const float2*)(x0 + 1 * N_NEUR + n2);
    float2 q   = *(const float2*)(x0 + 2 * N_NEUR + n2);
    float2 nn  = *(const float2*)(x0 + 3 * N_NEUR + n2);
    float2 e   = *(const float2*)(x0 + 4 * N_NEUR + n2);
    float2 f   = *(const float2*)(x0 + 5 * N_NEUR + n2);
    float2 cac = *(const float2*)(x0 + 6 * N_NEUR + n2);

    const float* inj = i_inj + n2;
    float* o = out + n2;

    // ---- prefetch first UNROLL currents as float2 (MLP=10 x 64-bit)
    float2 cur[UNROLL];
    #pragma unroll
    for (int u = 0; u < UNROLL; ++u)
        cur[u] = __ldcs((const float2*)(inj + u * N_NEUR));
    inj += UNROLL * N_NEUR;

    #pragma unroll 1
    for (int blk = 0; blk < NBLK; ++blk) {
        float2 nxt[UNROLL];
        if (blk < NBLK - 1) {
            #pragma unroll
            for (int u = 0; u < UNROLL; ++u)
                nxt[u] = __ldcs((const float2*)(inj + u * N_NEUR));
            inj += UNROLL * N_NEUR;
        }

        #pragma unroll
        for (int u = 0; u < UNROLL; ++u) {
            // two independent chains -> ptxas interleaves, fills MUFU/FFMA stalls
            hh_step(C, cur[u].x, V.x, p.x, q.x, nn.x, e.x, f.x, cac.x);
            hh_step(C, cur[u].y, V.y, p.y, q.y, nn.y, e.y, f.y, cac.y);

            // 7 x STG.64 streaming stores (coalesced, write-once)
            __stcs((float2*)(o + 0 * N_NEUR), V);
            __stcs((float2*)(o + 1 * N_NEUR), p);
            __stcs((float2*)(o + 2 * N_NEUR), q);
            __stcs((float2*)(o + 3 * N_NEUR), nn);
            __stcs((float2*)(o + 4 * N_NEUR), e);
            __stcs((float2*)(o + 5 * N_NEUR), f);
            __stcs((float2*)(o + 6 * N_NEUR), cac);
            o += 7 * N_NEUR;
        }

        #pragma unroll
        for (int u = 0; u < UNROLL; ++u)
            cur[u] = nxt[u];
    }
}

extern "C" void kernel_launch(void* const* d_in, const int* in_sizes, int n_in,
                              void* d_out, int out_size) {
    const float* i_inj  = (const float*)d_in[0];
    const float* x0     = (const float*)d_in[1];
    const float* params = (const float*)d_in[2];
    float* out = (float*)d_out;

    // 10000 threads, 2 adjacent neurons each; 313 one-warp blocks
    const int grid = (NPAIR + 31) / 32;
    hh_kernel<<<grid, 32>>>(i_inj, x0, params, out);
}

// round 7
// speedup vs baseline: 1.0159x; 1.0159x over previous
#include <cuda_runtime.h>

#define T_STEPS 500
#define N_NEUR  20000
#define NPAIR   (N_NEUR / 2)     // 10000 threads, 2 adjacent neurons each
#define DT      0.1f
#define UNROLL  10               // 500 = 10 * 50
#define NBLK    (T_STEPS / UNROLL)

typedef unsigned long long ull;

// ---- packed f32x2 primitives (sm_103a FFMA2 path; PTX-only) ----
__device__ __forceinline__ ull pack2(float lo, float hi) {
    ull d; asm("mov.b64 %0, {%1, %2};" : "=l"(d) : "f"(lo), "f"(hi)); return d;
}
__device__ __forceinline__ void unpack2(ull d, float& lo, float& hi) {
    asm("mov.b64 {%0, %1}, %2;" : "=f"(lo), "=f"(hi) : "l"(d));
}
__device__ __forceinline__ ull fma2(ull a, ull b, ull c) {
    ull d; asm("fma.rn.f32x2 %0, %1, %2, %3;" : "=l"(d) : "l"(a), "l"(b), "l"(c)); return d;
}
__device__ __forceinline__ ull add2(ull a, ull b) {
    ull d; asm("add.rn.f32x2 %0, %1, %2;" : "=l"(d) : "l"(a), "l"(b)); return d;
}
__device__ __forceinline__ ull mul2(ull a, ull b) {
    ull d; asm("mul.rn.f32x2 %0, %1, %2;" : "=l"(d) : "l"(a), "l"(b)); return d;
}
// packed tanh: 2 scalar MUFU on the register-pair halves
__device__ __forceinline__ ull tanh2(ull a) {
    float lo, hi; unpack2(a, lo, hi);
    float tl, th;
    asm("tanh.approx.f32 %0, %1;" : "=f"(tl) : "f"(lo));
    asm("tanh.approx.f32 %0, %1;" : "=f"(th) : "f"(hi));
    return pack2(tl, th);
}
__device__ __forceinline__ ull ldg_cs_u64(const float* p) {
    ull d; asm volatile("ld.global.cs.b64 %0, [%1];" : "=l"(d) : "l"(p)); return d;
}
__device__ __forceinline__ void stg_cs_u64(float* p, ull v) {
    asm volatile("st.global.cs.b64 [%0], %1;" :: "l"(p), "l"(v));
}

__global__ void __launch_bounds__(32, 1) hh_kernel(
    const float* __restrict__ i_inj,   // [T, N]
    const float* __restrict__ x0,      // [7, N]
    const float* __restrict__ params,  // [28]
    float* __restrict__ out)           // [T, 7, N]
{
    const int pi = blockIdx.x * 32 + threadIdx.x;   // pair index
    if (pi >= NPAIR) return;
    const int n2 = 2 * pi;

    // ---- scalar constant folding (once), then broadcast into packed pairs
    const float decay_ca = params[0];
    const float rho_ca   = params[1];
    const float p_tau = params[2],  p_scale = params[3],  p_mdp = params[4];
    const float q_tau = params[5],  q_scale = params[6],  q_mdp = params[7];
    const float n_tau = params[8],  n_scale = params[9],  n_mdp = params[10];
    const float f_tau = params[11], f_scale = params[12], f_mdp = params[13];
    const float e_tau = params[14], e_scale = params[15], e_mdp = params[16];
    const float h_alpha = params[17], h_scale = params[18], h_mdp = params[19];
    const float C_m = params[20], g_Ca = params[21], g_Ks = params[22];
    const float g_Kf = params[23], g_L = params[24];
    const float E_Ca = params[25], E_K = params[26], E_L = params[27];

    #define BC(x) pack2((x), (x))
    const ull pc1 = BC(0.5f/p_scale), pc0 = BC(-p_mdp*0.5f/p_scale);
    const ull qc1 = BC(0.5f/q_scale), qc0 = BC(-q_mdp*0.5f/q_scale);
    const ull nc1 = BC(0.5f/n_scale), nc0 = BC(-n_mdp*0.5f/n_scale);
    const ull fc1 = BC(0.5f/f_scale), fc0 = BC(-f_mdp*0.5f/f_scale);
    const ull ec1 = BC(0.5f/e_scale), ec0 = BC(-e_mdp*0.5f/e_scale);
    const ull hc1 = BC(0.5f/h_scale), hc0 = BC(-h_mdp*0.5f/h_scale);

    const ull Ap2 = BC(p_tau/(p_tau+DT)), Bp2 = BC(0.5f*DT/(p_tau+DT));
    const ull Aq2 = BC(q_tau/(q_tau+DT)), Bq2 = BC(0.5f*DT/(q_tau+DT));
    const ull An2 = BC(n_tau/(n_tau+DT)), Bn2 = BC(0.5f*DT/(n_tau+DT));
    const ull Af2 = BC(f_tau/(f_tau+DT)), Bf2 = BC(0.5f*DT/(f_tau+DT));
    const ull Ae2 = BC(e_tau/(e_tau+DT)), Be2 = BC(0.5f*DT/(e_tau+DT));

    const ull hb2 = BC(0.5f*h_alpha), ha2 = BC(1.0f - 0.5f*h_alpha);
    const ull gCa2 = BC(g_Ca), gKs2 = BC(g_Ks), gKf2 = BC(g_Kf);
    const ull nECa2 = BC(-E_Ca), nEK2 = BC(-E_K);
    // i_l = g_L*V - g_L*E_L  -> one packed FMA
    const ull gL2 = BC(g_L), gLEL2 = BC(-g_L * E_L);
    const ull dtCm2 = BC(DT / C_m);
    const ull cdec2 = BC(1.0f - DT / decay_ca);
    const ull nrho2 = BC(-rho_ca * DT);
    const ull m1_2  = BC(-1.0f);
    #undef BC

    // ---- packed initial state (adjacent neurons -> natural float2)
    #define LD2(v) pack2(x0[(v)*N_NEUR + n2], x0[(v)*N_NEUR + n2 + 1])
    ull V = LD2(0), p = LD2(1), q = LD2(2), nn = LD2(3), e = LD2(4), f = LD2(5), cac = LD2(6);
    #undef LD2

    const float* inj = i_inj + n2;
    float* o = out + n2;

    // ---- prefetch first UNROLL currents (LDG.64, MLP=10)
    ull cur[UNROLL];
    #pragma unroll
    for (int u = 0; u < UNROLL; ++u)
        cur[u] = ldg_cs_u64(inj + u * N_NEUR);
    inj += UNROLL * N_NEUR;

    #pragma unroll 1
    for (int blk = 0; blk < NBLK; ++blk) {
        ull nxt[UNROLL];
        if (blk < NBLK - 1) {
            #pragma unroll
            for (int u = 0; u < UNROLL; ++u)
                nxt[u] = ldg_cs_u64(inj + u * N_NEUR);
            inj += UNROLL * N_NEUR;
        }

        #pragma unroll
        for (int u = 0; u < UNROLL; ++u) {
            // h from OLD cac
            const ull h   = fma2(hb2, tanh2(fma2(cac, hc1, hc0)), ha2);

            const ull gef  = mul2(mul2(mul2(mul2(gCa2, e), e), f), h);
            const ull dVca = add2(V, nECa2);
            const ull i_ca = mul2(gef, dVca);
            const ull VmEK = add2(V, nEK2);
            const ull i_ks = mul2(mul2(gKs2, nn), VmEK);
            const ull p2v  = mul2(p, p);
            const ull i_kf = mul2(mul2(mul2(gKf2, mul2(p2v, p2v)), q), VmEK);
            const ull i_l  = fma2(gL2, V, gLEL2);

            const ull s    = add2(add2(i_ca, i_ks), add2(i_kf, i_l));
            const ull itot = fma2(s, m1_2, cur[u]);     // icur - s
            const ull dV   = mul2(itot, dtCm2);
            V = add2(V, dV);

            // i_ca2 = gef*(V_new - E_Ca) = i_ca + gef*dV
            const ull i_ca2 = fma2(gef, dV, i_ca);
            cac = fma2(cac, cdec2, mul2(i_ca2, nrho2));

            // 5 gates on UPDATED V: packed arg FMA -> 2x MUFU tanh -> 2 packed FMA
            p  = fma2(Bp2, tanh2(fma2(V, pc1, pc0)), fma2(Ap2, p,  Bp2));
            q  = fma2(Bq2, tanh2(fma2(V, qc1, qc0)), fma2(Aq2, q,  Bq2));
            e  = fma2(Be2, tanh2(fma2(V, ec1, ec0)), fma2(Ae2, e,  Be2));
            f  = fma2(Bf2, tanh2(fma2(V, fc1, fc0)), fma2(Af2, f,  Bf2));
            nn = fma2(Bn2, tanh2(fma2(V, nc1, nc0)), fma2(An2, nn, Bn2));

            // 7 x STG.64 streaming stores
            stg_cs_u64(o + 0 * N_NEUR, V);
            stg_cs_u64(o + 1 * N_NEUR, p);
            stg_cs_u64(o + 2 * N_NEUR, q);
            stg_cs_u64(o + 3 * N_NEUR, nn);
            stg_cs_u64(o + 4 * N_NEUR, e);
            stg_cs_u64(o + 5 * N_NEUR, f);
            stg_cs_u64(o + 6 * N_NEUR, cac);
            o += 7 * N_NEUR;
        }

        #pragma unroll
        for (int u = 0; u < UNROLL; ++u)
            cur[u] = nxt[u];
    }
}

extern "C" void kernel_launch(void* const* d_in, const int* in_sizes, int n_in,
                              void* d_out, int out_size) {
    const float* i_inj  = (const float*)d_in[0];
    const float* x0     = (const float*)d_in[1];
    const float* params = (const float*)d_in[2];
    float* out = (float*)d_out;

    const int grid = (NPAIR + 31) / 32;   // 313 one-warp blocks, 2 neurons/thread
    hh_kernel<<<grid, 32>>>(i_inj, x0, params, out);
}

// round 8
// speedup vs baseline: 1.1506x; 1.1326x over previous
#include <cuda_runtime.h>

#define T_STEPS 500
#define N_NEUR  20000
#define DT      0.1f
#define UNROLL  10               // 500 = 10 * 50
#define NBLK    (T_STEPS / UNROLL)
#define NGRP    625              // neuron groups of 32

__device__ __forceinline__ float fast_tanh(float t) {
    float r;
    asm("tanh.approx.f32 %0, %1;" : "=f"(r) : "f"(t));
    return r;
}

__global__ void __launch_bounds__(32, 16) hh_kernel(
    const float* __restrict__ i_inj,   // [T, N]
    const float* __restrict__ x0,      // [7, N]
    const float* __restrict__ params,  // [28]
    float* __restrict__ out)           // [T, 7, N]
{
    // 1250 blocks: blocks [0,625) = replica 0, [625,1250) = replica 1.
    // Both replicas integrate the same 32 neurons; stores are split 4/3.
    const int rep = (blockIdx.x >= NGRP) ? 1 : 0;
    const int grp = blockIdx.x - rep * NGRP;
    const int n   = grp * 32 + threadIdx.x;

    // ---- fold constants
    const float decay_ca = params[0];
    const float rho_ca   = params[1];
    const float p_tau = params[2],  p_scale = params[3],  p_mdp = params[4];
    const float q_tau = params[5],  q_scale = params[6],  q_mdp = params[7];
    const float n_tau = params[8],  n_scale = params[9],  n_mdp = params[10];
    const float f_tau = params[11], f_scale = params[12], f_mdp = params[13];
    const float e_tau = params[14], e_scale = params[15], e_mdp = params[16];
    const float h_alpha = params[17], h_scale = params[18], h_mdp = params[19];
    const float C_m = params[20], g_Ca = params[21], g_Ks = params[22];
    const float g_Kf = params[23], g_L = params[24];
    const float E_Ca = params[25], E_K = params[26], E_L = params[27];

    const float p_c1 = 0.5f / p_scale, p_c0 = -p_mdp * 0.5f / p_scale;
    const float q_c1 = 0.5f / q_scale, q_c0 = -q_mdp * 0.5f / q_scale;
    const float n_c1 = 0.5f / n_scale, n_c0 = -n_mdp * 0.5f / n_scale;
    const float f_c1 = 0.5f / f_scale, f_c0 = -f_mdp * 0.5f / f_scale;
    const float e_c1 = 0.5f / e_scale, e_c0 = -e_mdp * 0.5f / e_scale;
    const float h_c1 = 0.5f / h_scale, h_c0 = -h_mdp * 0.5f / h_scale;

    const float Ap = p_tau / (p_tau + DT), Bp = 0.5f * DT / (p_tau + DT);
    const float Aq = q_tau / (q_tau + DT), Bq = 0.5f * DT / (q_tau + DT);
    const float An = n_tau / (n_tau + DT), Bn = 0.5f * DT / (n_tau + DT);
    const float Af = f_tau / (f_tau + DT), Bf = 0.5f * DT / (f_tau + DT);
    const float Ae = e_tau / (e_tau + DT), Be = 0.5f * DT / (e_tau + DT);

    const float h_b = 0.5f * h_alpha;
    const float h_a = 1.0f - h_b;
    const float dt_over_Cm = DT / C_m;
    const float cdecay     = 1.0f - DT / decay_ca;
    const float rho_dt     = rho_ca * DT;

    // ---- initial state
    float V   = x0[0 * N_NEUR + n];
    float p   = x0[1 * N_NEUR + n];
    float q   = x0[2 * N_NEUR + n];
    float nn  = x0[3 * N_NEUR + n];
    float e   = x0[4 * N_NEUR + n];
    float f   = x0[5 * N_NEUR + n];
    float cac = x0[6 * N_NEUR + n];

    const float* inj = i_inj + n;
    float* o = out + n;

    // ---- prefetch first UNROLL currents (MLP=10)
    float cur[UNROLL];
    #pragma unroll
    for (int u = 0; u < UNROLL; ++u)
        cur[u] = __ldg(inj + u * N_NEUR);     // .ca: second replica hits L2
    inj += UNROLL * N_NEUR;

    #pragma unroll 1
    for (int blk = 0; blk < NBLK; ++blk) {
        float nxt[UNROLL];
        if (blk < NBLK - 1) {
            #pragma unroll
            for (int u = 0; u < UNROLL; ++u)
                nxt[u] = __ldg(inj + u * N_NEUR);
            inj += UNROLL * N_NEUR;
        }

        #pragma unroll
        for (int u = 0; u < UNROLL; ++u) {
            const float icur = cur[u];

            // h from OLD cac
            const float h = fmaf(h_b, fast_tanh(fmaf(cac, h_c1, h_c0)), h_a);

            const float gef  = g_Ca * e * e * f * h;
            const float i_ca = gef * (V - E_Ca);
            const float VmEK = V - E_K;
            const float i_ks = g_Ks * nn * VmEK;
            const float p2   = p * p;
            const float i_kf = g_Kf * p2 * p2 * q * VmEK;
            const float i_l  = g_L * (V - E_L);

            const float itot = icur - ((i_ca + i_ks) + (i_kf + i_l));
            const float dV   = itot * dt_over_Cm;
            V += dV;

            // i_ca2 = gef*(V_new - E_Ca) = i_ca + gef*dV
            const float i_ca2 = fmaf(gef, dV, i_ca);
            cac = fmaf(cac, cdecay, -i_ca2 * rho_dt);

            // 5 independent gate chains on UPDATED V
            p  = fmaf(Bp, fast_tanh(fmaf(V, p_c1, p_c0)), fmaf(Ap, p,  Bp));
            q  = fmaf(Bq, fast_tanh(fmaf(V, q_c1, q_c0)), fmaf(Aq, q,  Bq));
            e  = fmaf(Be, fast_tanh(fmaf(V, e_c1, e_c0)), fmaf(Ae, e,  Be));
            f  = fmaf(Bf, fast_tanh(fmaf(V, f_c1, f_c0)), fmaf(Af, f,  Bf));
            nn = fmaf(Bn, fast_tanh(fmaf(V, n_c1, n_c0)), fmaf(An, nn, Bn));

            // split stores: replica 0 -> V,p,q,n ; replica 1 -> e,f,cac
            if (rep == 0) {
                __stcs(o + 0 * N_NEUR, V);
                __stcs(o + 1 * N_NEUR, p);
                __stcs(o + 2 * N_NEUR, q);
                __stcs(o + 3 * N_NEUR, nn);
            } else {
                __stcs(o + 4 * N_NEUR, e);
                __stcs(o + 5 * N_NEUR, f);
                __stcs(o + 6 * N_NEUR, cac);
            }
            o += 7 * N_NEUR;
        }

        #pragma unroll
        for (int u = 0; u < UNROLL; ++u)
            cur[u] = nxt[u];
    }
}

extern "C" void kernel_launch(void* const* d_in, const int* in_sizes, int n_in,
                              void* d_out, int out_size) {
    const float* i_inj  = (const float*)d_in[0];
    const float* x0     = (const float*)d_in[1];
    const float* params = (const float*)d_in[2];
    float* out = (float*)d_out;

    // 2x replicated compute: 1250 one-warp blocks (~2.1 warps/SMSP),
    // dense co-resident compute streams hide each other's latency stalls.
    hh_kernel<<<2 * NGRP, 32>>>(i_inj, x0, params, out);
}

// round 9
// speedup vs baseline: 1.4015x; 1.2181x over previous
#include <cuda_runtime.h>

#define T_STEPS 500
#define N_NEUR  20000
#define NPAIR   (N_NEUR / 2)     // 10000 pairs, 2 adjacent neurons each
#define NGRP    313              // ceil(10000/32) pair-groups of 32
#define NREP    279              // groups 0..278 get a second (replica) warp
#define DT      0.1f
#define UNROLL  10               // 500 = 10 * 50
#define NBLK    (T_STEPS / UNROLL)

typedef unsigned long long ull;

// ---- packed f32x2 primitives (sm_103a FFMA2 path; PTX-only) ----
__device__ __forceinline__ ull pack2(float lo, float hi) {
    ull d; asm("mov.b64 %0, {%1, %2};" : "=l"(d) : "f"(lo), "f"(hi)); return d;
}
__device__ __forceinline__ void unpack2(ull d, float& lo, float& hi) {
    asm("mov.b64 {%0, %1}, %2;" : "=f"(lo), "=f"(hi) : "l"(d));
}
__device__ __forceinline__ ull fma2(ull a, ull b, ull c) {
    ull d; asm("fma.rn.f32x2 %0, %1, %2, %3;" : "=l"(d) : "l"(a), "l"(b), "l"(c)); return d;
}
__device__ __forceinline__ ull add2(ull a, ull b) {
    ull d; asm("add.rn.f32x2 %0, %1, %2;" : "=l"(d) : "l"(a), "l"(b)); return d;
}
__device__ __forceinline__ ull mul2(ull a, ull b) {
    ull d; asm("mul.rn.f32x2 %0, %1, %2;" : "=l"(d) : "l"(a), "l"(b)); return d;
}
__device__ __forceinline__ ull tanh2(ull a) {
    float lo, hi; unpack2(a, lo, hi);
    float tl, th;
    asm("tanh.approx.f32 %0, %1;" : "=f"(tl) : "f"(lo));
    asm("tanh.approx.f32 %0, %1;" : "=f"(th) : "f"(hi));
    return pack2(tl, th);
}
__device__ __forceinline__ ull ldg_ca_u64(const float* p) {
    ull d; asm volatile("ld.global.ca.b64 %0, [%1];" : "=l"(d) : "l"(p)); return d;
}
__device__ __forceinline__ void stg_cs_u64(float* p, ull v) {
    asm volatile("st.global.cs.b64 [%0], %1;" :: "l"(p), "l"(v));
}

__global__ void __launch_bounds__(32, 4) hh_kernel(
    const float* __restrict__ i_inj,   // [T, N]
    const float* __restrict__ x0,      // [7, N]
    const float* __restrict__ params,  // [28]
    float* __restrict__ out)           // [T, 7, N]
{
    // 592 one-warp blocks = 4 per SM = 1 per SMSP (perfectly balanced wave-1).
    //   bid <  279          : replica 0 of group bid   (stores V,p,q,n)
    //   279 <= bid < 313    : solo warp of group bid   (stores all 7)
    //   bid >= 313          : replica 1 of group bid-313 (stores e,f,cac)
    const int bid = blockIdx.x;
    int grp, role;                     // role: 0=rep0, 1=solo, 2=rep1
    if (bid < NGRP) { grp = bid;        role = (bid < NREP) ? 0 : 1; }
    else            { grp = bid - NGRP; role = 2; }

    const bool store_lo = (role != 2);
    const bool store_hi = (role != 0);

    const int pi = grp * 32 + threadIdx.x;
    if (pi >= NPAIR) return;
    const int n2 = 2 * pi;

    // ---- scalar constant folding, then broadcast into packed pairs
    const float decay_ca = params[0];
    const float rho_ca   = params[1];
    const float p_tau = params[2],  p_scale = params[3],  p_mdp = params[4];
    const float q_tau = params[5],  q_scale = params[6],  q_mdp = params[7];
    const float n_tau = params[8],  n_scale = params[9],  n_mdp = params[10];
    const float f_tau = params[11], f_scale = params[12], f_mdp = params[13];
    const float e_tau = params[14], e_scale = params[15], e_mdp = params[16];
    const float h_alpha = params[17], h_scale = params[18], h_mdp = params[19];
    const float C_m = params[20], g_Ca = params[21], g_Ks = params[22];
    const float g_Kf = params[23], g_L = params[24];
    const float E_Ca = params[25], E_K = params[26], E_L = params[27];

    #define BC(x) pack2((x), (x))
    const ull pc1 = BC(0.5f/p_scale), pc0 = BC(-p_mdp*0.5f/p_scale);
    const ull qc1 = BC(0.5f/q_scale), qc0 = BC(-q_mdp*0.5f/q_scale);
    const ull nc1 = BC(0.5f/n_scale), nc0 = BC(-n_mdp*0.5f/n_scale);
    const ull fc1 = BC(0.5f/f_scale), fc0 = BC(-f_mdp*0.5f/f_scale);
    const ull ec1 = BC(0.5f/e_scale), ec0 = BC(-e_mdp*0.5f/e_scale);
    const ull hc1 = BC(0.5f/h_scale), hc0 = BC(-h_mdp*0.5f/h_scale);

    const ull Ap2 = BC(p_tau/(p_tau+DT)), Bp2 = BC(0.5f*DT/(p_tau+DT));
    const ull Aq2 = BC(q_tau/(q_tau+DT)), Bq2 = BC(0.5f*DT/(q_tau+DT));
    const ull An2 = BC(n_tau/(n_tau+DT)), Bn2 = BC(0.5f*DT/(n_tau+DT));
    const ull Af2 = BC(f_tau/(f_tau+DT)), Bf2 = BC(0.5f*DT/(f_tau+DT));
    const ull Ae2 = BC(e_tau/(e_tau+DT)), Be2 = BC(0.5f*DT/(e_tau+DT));

    const ull hb2 = BC(0.5f*h_alpha), ha2 = BC(1.0f - 0.5f*h_alpha);
    const ull gCa2 = BC(g_Ca), gKs2 = BC(g_Ks), gKf2 = BC(g_Kf);
    const ull nECa2 = BC(-E_Ca), nEK2 = BC(-E_K);
    const ull gL2 = BC(g_L), gLEL2 = BC(-g_L * E_L);   // i_l = g_L*V - g_L*E_L
    const ull dtCm2 = BC(DT / C_m);
    const ull cdec2 = BC(1.0f - DT / decay_ca);
    const ull nrho2 = BC(-rho_ca * DT);
    const ull m1_2  = BC(-1.0f);
    #undef BC

    // ---- packed initial state (adjacent neurons -> natural float2)
    #define LD2(v) pack2(x0[(v)*N_NEUR + n2], x0[(v)*N_NEUR + n2 + 1])
    ull V = LD2(0), p = LD2(1), q = LD2(2), nn = LD2(3), e = LD2(4), f = LD2(5), cac = LD2(6);
    #undef LD2

    const float* inj = i_inj + n2;
    float* o = out + n2;

    // ---- prefetch first UNROLL currents (LDG.64 .ca -> replica hits L2, MLP=10)
    ull cur[UNROLL];
    #pragma unroll
    for (int u = 0; u < UNROLL; ++u)
        cur[u] = ldg_ca_u64(inj + u * N_NEUR);
    inj += UNROLL * N_NEUR;

    #pragma unroll 1
    for (int blk = 0; blk < NBLK; ++blk) {
        ull nxt[UNROLL];
        if (blk < NBLK - 1) {
            #pragma unroll
            for (int u = 0; u < UNROLL; ++u)
                nxt[u] = ldg_ca_u64(inj + u * N_NEUR);
            inj += UNROLL * N_NEUR;
        }

        #pragma unroll
        for (int u = 0; u < UNROLL; ++u) {
            // h from OLD cac
            const ull h = fma2(hb2, tanh2(fma2(cac, hc1, hc0)), ha2);

            const ull gef  = mul2(mul2(mul2(mul2(gCa2, e), e), f), h);
            const ull i_ca = mul2(gef, add2(V, nECa2));
            const ull VmEK = add2(V, nEK2);
            const ull i_ks = mul2(mul2(gKs2, nn), VmEK);
            const ull p2v  = mul2(p, p);
            const ull i_kf = mul2(mul2(mul2(gKf2, mul2(p2v, p2v)), q), VmEK);
            const ull i_l  = fma2(gL2, V, gLEL2);

            const ull s    = add2(add2(i_ca, i_ks), add2(i_kf, i_l));
            const ull itot = fma2(s, m1_2, cur[u]);     // icur - s
            const ull dV   = mul2(itot, dtCm2);
            V = add2(V, dV);

            // i_ca2 = gef*(V_new - E_Ca) = i_ca + gef*dV
            const ull i_ca2 = fma2(gef, dV, i_ca);
            cac = fma2(cac, cdec2, mul2(i_ca2, nrho2));

            // 5 gates on UPDATED V
            p  = fma2(Bp2, tanh2(fma2(V, pc1, pc0)), fma2(Ap2, p,  Bp2));
            q  = fma2(Bq2, tanh2(fma2(V, qc1, qc0)), fma2(Aq2, q,  Bq2));
            e  = fma2(Be2, tanh2(fma2(V, ec1, ec0)), fma2(Ae2, e,  Be2));
            f  = fma2(Bf2, tanh2(fma2(V, fc1, fc0)), fma2(Af2, f,  Bf2));
            nn = fma2(Bn2, tanh2(fma2(V, nc1, nc0)), fma2(An2, nn, Bn2));

            // split streaming stores (STG.64)
            if (store_lo) {
                stg_cs_u64(o + 0 * N_NEUR, V);
                stg_cs_u64(o + 1 * N_NEUR, p);
                stg_cs_u64(o + 2 * N_NEUR, q);
                stg_cs_u64(o + 3 * N_NEUR, nn);
            }
            if (store_hi) {
                stg_cs_u64(o + 4 * N_NEUR, e);
                stg_cs_u64(o + 5 * N_NEUR, f);
                stg_cs_u64(o + 6 * N_NEUR, cac);
            }
            o += 7 * N_NEUR;
        }

        #pragma unroll
        for (int u = 0; u < UNROLL; ++u)
            cur[u] = nxt[u];
    }
}

extern "C" void kernel_launch(void* const* d_in, const int* in_sizes, int n_in,
                              void* d_out, int out_size) {
    const float* i_inj  = (const float*)d_in[0];
    const float* x0     = (const float*)d_in[1];
    const float* params = (const float*)d_in[2];
    float* out = (float*)d_out;

    // 592 one-warp blocks = 313 real groups + 279 replicas
    // -> exactly 4 blocks per SM, 1 warp per SMSP, zero placement imbalance
    hh_kernel<<<NGRP + NREP, 32>>>(i_inj, x0, params, out);
}